// round 15
// baseline (speedup 1.0000x reference)
#include <cuda_runtime.h>
#include <cuda_fp16.h>
#include <mma.h>
#include <cstdint>

// UpConvBlock: y = ConvTranspose2d(x, w1, k=4, s=2, p=1) + b1
//              out = PAC-3x3(y, guide, w2) + b2
// R15: R13 base (4 CTAs/SM, single-buffer stages) + THREE shifted fp16 copies
// (A=+0, B=+1, C=+2) of padded x and y so all tap shifts become aligned u64
// loads: B staging is 8x(LDG.64+STS.64) per thread per stage (was 16x .32).

#define H1 64
#define W1 64
#define CIN 256
#define CMID 128
#define H2 128
#define W2 128
#define BATCH 4

#define XP_H 66
#define XP_W 68
#define XP_CH (XP_H * XP_W)          // 4488
#define YP_H 130
#define YP_W 132
#define YP_CH (YP_H * YP_W)          // 17160

typedef unsigned long long u64;
typedef unsigned int u32;

using namespace nvcuda;

__device__ __forceinline__ u32 smem_u32(const void* p) {
    u32 a; asm("{ .reg .u64 t; cvta.to.shared.u64 t, %1; cvt.u32.u64 %0, t; }" : "=r"(a) : "l"(p));
    return a;
}
__device__ __forceinline__ void cpasync16(u32 dst, const void* src) {
    asm volatile("cp.async.ca.shared.global [%0], [%1], 16;" :: "r"(dst), "l"(src));
}
__device__ __forceinline__ void cpasync_wait() {
    asm volatile("cp.async.commit_group;\n\tcp.async.wait_group 0;" ::: "memory");
}

// ---------------- scratch globals ----------------
__device__ __align__(8) __half g_xS[3][BATCH * CIN * XP_CH];   // shifts 0/1/2
__device__ __align__(8) __half g_yS[3][BATCH * CMID * YP_CH];  // shifts 0/1/2
__device__ __align__(128) __half g_w1[4 * 8 * 128 * 128];      // [par][kc][o][krow]
__device__ __align__(128) __half g_w2[9 * 128 * 128];          // [ij][o][c]

// smem: A [128][136] halves, B [128][72] halves
#define SA2 136
#define SB 72
#define OFF_A 0
#define OFF_B 34816
#define KS32 16384                       // pac phase A fp32 scratch (in A region)
#define OFF_KSH 53248                    // pac half2 [9][32]
#define CONVT_SMEM 53248
#define PAC_SMEM   54400

// ---------------------------------------------------------------------------
// Prep kernels
// ---------------------------------------------------------------------------
__global__ void prep_w1(const float* __restrict__ w1) {
    int idx = blockIdx.x * 256 + threadIdx.x;
    if (idx >= 4 * 8 * 128 * 128) return;
    int kr = idx & 127;
    int o  = (idx >> 7) & 127;
    int kc = (idx >> 14) & 7;
    int par = idx >> 17;
    int di = par >> 1, dj = par & 1;
    int c = kc * 32 + (kr >> 2);
    int tap = kr & 3;
    int t = tap >> 1, u = tap & 1;
    g_w1[idx] = __float2half_rn(w1[(c * CMID + o) * 16 + (3 - di - 2 * t) * 4 + (3 - dj - 2 * u)]);
}

__global__ void prep_w2(const float* __restrict__ w2) {
    int idx = blockIdx.x * 256 + threadIdx.x;
    if (idx >= 9 * 128 * 128) return;
    int c  = idx & 127;
    int o  = (idx >> 7) & 127;
    int ij = idx >> 14;
    int i = ij / 3, j = ij % 3;
    g_w2[idx] = __float2half_rn(w2[(c * CMID + o) * 9 + (2 - i) * 3 + (2 - j)]);
}

__global__ void pad_xk(const float* __restrict__ x) {
    int idx = blockIdx.x * 256 + threadIdx.x;
    if (idx >= BATCH * CIN * XP_CH) return;
    int col = idx % XP_W;
    int r   = (idx / XP_W) % XP_H;
    int bc  = idx / XP_CH;
    int h = r - 1;
    bool okh = (unsigned)h < (unsigned)H1;
#pragma unroll
    for (int s = 0; s < 3; s++) {
        int w = col - 1 + s;
        float v = (okh && (unsigned)w < (unsigned)W1) ? x[bc * (H1 * W1) + h * W1 + w] : 0.f;
        g_xS[s][idx] = __float2half_rn(v);
    }
}

__global__ void zero_y() {
    int idx = blockIdx.x * 256 + threadIdx.x;
    if (idx >= (BATCH * CMID * YP_CH) / 4) return;
    ((u64*)g_yS[0])[idx] = 0ull;
    ((u64*)g_yS[1])[idx] = 0ull;
    ((u64*)g_yS[2])[idx] = 0ull;
}

// ---------------------------------------------------------------------------
// MMA stage: A[128][136], B[128][72], 8 k-steps.
// ---------------------------------------------------------------------------
template<typename AccT>
__device__ __forceinline__ void mma_stage(const char* smem, int mo, int np, AccT (&acc)[2][2]) {
#pragma unroll
    for (int k0 = 0; k0 < 8; k0++) {
        const __half* B = (const __half*)(smem + OFF_B);
        const __half* A = (const __half*)(smem + OFF_A);
        wmma::fragment<wmma::matrix_b, 16, 16, 16, __half, wmma::row_major> bf[2];
        wmma::fragment<wmma::matrix_a, 16, 16, 16, __half, wmma::row_major> af[2];
        wmma::load_matrix_sync(bf[0], B + (k0 * 16) * SB + np, SB);
        wmma::load_matrix_sync(bf[1], B + (k0 * 16) * SB + np + 16, SB);
        wmma::load_matrix_sync(af[0], A + mo * SA2 + k0 * 16, SA2);
        wmma::load_matrix_sync(af[1], A + (mo + 16) * SA2 + k0 * 16, SA2);
#pragma unroll
        for (int m = 0; m < 2; m++)
#pragma unroll
            for (int n = 0; n < 2; n++)
                wmma::mma_sync(acc[m][n], af[m], bf[n], acc[m][n]);
    }
}

// ---------------------------------------------------------------------------
// Kernel 1: conv_transpose (parity decomposition). Block: 128o x 64px.
// K = 1024 in 8 chunks of 128 (32c x 4taps). Staging: 8x u64 copies/thread.
// Thread map: pxq = tid&15 (4-px quad), krow_base = tid>>4, krow = base+16q.
// ---------------------------------------------------------------------------
__global__ __launch_bounds__(256, 4) void convt_wmma(const float* __restrict__ b1) {
    extern __shared__ __align__(128) char smem[];
    const u32 sb = smem_u32(smem);
    const int tid = threadIdx.x;
    const int wid = tid >> 5;
    const int mo = (wid & 3) * 32;
    const int np = (wid >> 2) * 32;

    const int bz = blockIdx.z;
    const int b  = bz >> 2;
    const int par = bz & 3;
    const int di = par >> 1, dj = par & 1;
    const int i0 = blockIdx.y * 8;
    const int j0 = blockIdx.x * 8;

    // staging coords
    const int pxq = tid & 15;                // quad: pixels pxq*4..pxq*4+3
    const int r = pxq >> 1;
    const int cw = (pxq & 1) * 4;
    const int kb = tid >> 4;                 // krow_base; krow = kb + 16q
    const int tap = kb & 3;                  // q-invariant
    const int t = tap >> 1, u = tap & 1;
    const int shift = dj + u;                // 0..2 -> copy select

    const u64* xw = (const u64*)(g_xS[shift]
                    + ((u64)(b * CIN + (kb >> 2)) * XP_CH)
                    + (i0 + di + r + t) * XP_W + (j0 + cw));
    char* bsm = smem + OFF_B + kb * (SB * 2) + pxq * 8;

    wmma::fragment<wmma::accumulator, 16, 16, 16, float> acc[2][2];
#pragma unroll
    for (int m = 0; m < 2; m++)
#pragma unroll
        for (int n = 0; n < 2; n++) wmma::fill_fragment(acc[m][n], 0.f);

    for (int kc = 0; kc < 8; kc++) {
        __syncthreads();
        // A: cp.async weights, 128 rows x 256B
        {
            const __half* wA = g_w1 + (par * 8 + kc) * 16384;
#pragma unroll
            for (int q = 0; q < 8; q++) {
                int p = tid + q * 256;
                int o = p >> 4, ch = p & 15;
                cpasync16(sb + OFF_A + (u32)(o * (SA2 * 2) + ch * 16), wA + o * 128 + ch * 8);
            }
        }
        // B: aligned u64 copies (per-q channel stride = 4 ch = XP_CH u64 words)
        const u64* xs = xw + (u64)kc * (8 * XP_CH);
#pragma unroll
        for (int q = 0; q < 8; q++) {
            *(u64*)(bsm + q * (16 * SB * 2)) = xs[0];
            xs += XP_CH;
        }
        cpasync_wait();
        __syncthreads();

        mma_stage(smem, mo, np, acc);
    }

    // epilogue: fbuf [128][72] fp32, parity scatter into 3 fp16 y copies
    __syncthreads();
    float* fbuf = (float*)smem;
#pragma unroll
    for (int m = 0; m < 2; m++)
#pragma unroll
        for (int n = 0; n < 2; n++)
            wmma::store_matrix_sync(fbuf + (mo + m * 16) * SB + np + n * 16,
                                    acc[m][n], SB, wmma::mem_row_major);
    __syncthreads();
    for (int idx = tid; idx < 8192; idx += 256) {
        int o = idx >> 6;
        int n = idx & 63;
        int rr = n >> 3, cc = n & 7;
        float v = fbuf[o * SB + n] + __ldg(&b1[o]);
        __half hv = __float2half_rn(v);
        u64 base = (u64)(b * CMID + o) * YP_CH
                 + (2 * (i0 + rr) + di + 1) * YP_W + 2 * (j0 + cc) + dj + 1;
        g_yS[0][base] = hv;
        g_yS[1][base - 1] = hv;
        g_yS[2][base - 2] = hv;
    }
}

// ---------------------------------------------------------------------------
// Kernel 2: PAC 3x3. Block: 128o x 64px. 9 ij stages, K=128 each.
// Staging: 8x (LDG.64 + 2 HMUL2 + STS.64) per thread per stage.
// ---------------------------------------------------------------------------
__global__ __launch_bounds__(256, 4) void pac_wmma(const float* __restrict__ guide,
                                                   const float* __restrict__ b2,
                                                   float* __restrict__ out) {
    extern __shared__ __align__(128) char smem[];
    const u32 sb = smem_u32(smem);
    const int tid = threadIdx.x;
    const int wid = tid >> 5;
    const int mo = (wid & 3) * 32;
    const int np = (wid >> 2) * 32;

    const int b  = blockIdx.z;
    const int h0 = blockIdx.y * 8;
    const int w0 = blockIdx.x * 8;

    float* ks32 = (float*)(smem + KS32);
    u32*   ksh  = (u32*)(smem + OFF_KSH);
    float* gs   = (float*)smem;

    // ---- Phase A: guide kernel ----
    for (int tt = tid; tt < 576; tt += 256) ks32[tt] = 0.f;

    for (int cc = 0; cc < CMID; cc += 32) {
        __syncthreads();
        for (int idx = tid; idx < 3200; idx += 256) {
            int c = idx / 100;
            int rr = (idx % 100) / 10;
            int col = idx % 10;
            int gh = h0 - 1 + rr, gw = w0 - 1 + col;
            float v = 0.f;
            if ((unsigned)gh < (unsigned)H2 && (unsigned)gw < (unsigned)W2)
                v = guide[((b * CMID + cc + c) * H2 + gh) * W2 + gw];
            gs[c * 120 + rr * 12 + col] = v;
        }
        __syncthreads();
        for (int idx = tid; idx < 576; idx += 256) {
            int ij = idx >> 6;
            int p  = idx & 63;
            int i = ij / 3, j = ij % 3;
            int rr = p >> 3, cww = p & 7;
            float s = 0.f;
#pragma unroll
            for (int c = 0; c < 32; c++) {
                float d = gs[c * 120 + (rr + i) * 12 + (cww + j)] - gs[c * 120 + (rr + 1) * 12 + (cww + 1)];
                s += d * d;
            }
            ks32[idx] += s;
        }
    }
    __syncthreads();
    for (int tt = tid; tt < 576; tt += 256) ks32[tt] = __expf(-0.5f * ks32[tt]);
    __syncthreads();
    for (int tt = tid; tt < 288; tt += 256) {
        int ij = tt >> 5, p = tt & 31;
        __half2 hk = __floats2half2_rn(ks32[ij * 64 + 2 * p], ks32[ij * 64 + 2 * p + 1]);
        ksh[tt] = *(u32*)&hk;
    }
    __syncthreads();

    // ---- Phase B: 9 ij stages ----
    const int pxq = tid & 15;                // quad: pixel-pairs 2*pxq, 2*pxq+1
    const int r = pxq >> 1;
    const int cw = (pxq & 1) * 4;
    const int kb = tid >> 4;                 // channel base; c = kb + 16q
    char* bsm = smem + OFF_B + kb * (SB * 2) + pxq * 8;

    wmma::fragment<wmma::accumulator, 16, 16, 16, float> acc[2][2];
#pragma unroll
    for (int m = 0; m < 2; m++)
#pragma unroll
        for (int n = 0; n < 2; n++) wmma::fill_fragment(acc[m][n], 0.f);

    for (int ij = 0; ij < 9; ij++) {
        const int i = ij / 3, j = ij % 3;
        __syncthreads();
        // A: cp.async weights
        {
            const __half* wA = g_w2 + ij * 16384;
#pragma unroll
            for (int q = 0; q < 8; q++) {
                int p = tid + q * 256;
                int o = p >> 4, ch = p & 15;
                cpasync16(sb + OFF_A + (u32)(o * (SA2 * 2) + ch * 16), wA + o * 128 + ch * 8);
            }
        }
        // B = y * k: aligned u64 load + 2x HMUL2 (copy select by j)
        const u32 kk0 = ksh[ij * 32 + 2 * pxq];
        const u32 kk1 = ksh[ij * 32 + 2 * pxq + 1];
        const __half2 hk0 = *(const __half2*)&kk0;
        const __half2 hk1 = *(const __half2*)&kk1;
        const u64* yw = (const u64*)(g_yS[j]
                        + ((u64)(b * CMID + kb) * YP_CH)
                        + (h0 + r + i) * YP_W + (w0 + cw));
#pragma unroll
        for (int q = 0; q < 8; q++) {
            u64 raw = yw[0];
            __half2 lo = __hmul2(*(const __half2*)&raw, hk0);
            __half2 hi = __hmul2(*((const __half2*)&raw + 1), hk1);
            u64 outv = ((u64)*(u32*)&hi << 32) | *(u32*)&lo;
            *(u64*)(bsm + q * (16 * SB * 2)) = outv;
            yw += 4 * YP_CH;              // 16 channels = 16*YP_CH halves
        }
        cpasync_wait();
        __syncthreads();

        mma_stage(smem, mo, np, acc);
    }

    // ---- Epilogue ----
    __syncthreads();
    float* fbuf = (float*)smem;
#pragma unroll
    for (int m = 0; m < 2; m++)
#pragma unroll
        for (int n = 0; n < 2; n++)
            wmma::store_matrix_sync(fbuf + (mo + m * 16) * SB + np + n * 16,
                                    acc[m][n], SB, wmma::mem_row_major);
    __syncthreads();
    for (int idx = tid; idx < 8192; idx += 256) {
        int o = idx >> 6;
        int n = idx & 63;
        float v = fbuf[o * SB + n] + __ldg(&b2[o]);
        out[((b * CMID + o) * H2 + h0 + (n >> 3)) * W2 + w0 + (n & 7)] = v;
    }
}

extern "C" void kernel_launch(void* const* d_in, const int* in_sizes, int n_in,
                              void* d_out, int out_size) {
    const float* x     = (const float*)d_in[0];
    const float* guide = (const float*)d_in[1];
    const float* w1    = (const float*)d_in[2];
    const float* b1    = (const float*)d_in[3];
    const float* w2    = (const float*)d_in[4];
    const float* b2    = (const float*)d_in[5];
    float* out = (float*)d_out;

    cudaFuncSetAttribute(convt_wmma, cudaFuncAttributeMaxDynamicSharedMemorySize, CONVT_SMEM);
    cudaFuncSetAttribute(pac_wmma, cudaFuncAttributeMaxDynamicSharedMemorySize, PAC_SMEM);

    prep_w1<<<(4 * 8 * 128 * 128 + 255) / 256, 256>>>(w1);
    prep_w2<<<(9 * 128 * 128 + 255) / 256, 256>>>(w2);
    pad_xk<<<(BATCH * CIN * XP_CH + 255) / 256, 256>>>(x);
    zero_y<<<((BATCH * CMID * YP_CH) / 4 + 255) / 256, 256>>>();
    convt_wmma<<<dim3(8, 8, BATCH * 4), 256, CONVT_SMEM>>>(b1);
    pac_wmma<<<dim3(16, 16, BATCH), 256, PAC_SMEM>>>(guide, b2, out);
}

// round 16
// speedup vs baseline: 1.5332x; 1.5332x over previous
#include <cuda_runtime.h>
#include <cuda_fp16.h>
#include <mma.h>
#include <cstdint>

// UpConvBlock: y = ConvTranspose2d(x, w1, k=4, s=2, p=1) + b1
//              out = PAC-3x3(y, guide, w2) + b2
// R16: R13 (best: 331.9us) verbatim + border-only y zeroing + merged weight
// prep. fp16 HMMA, shifted fp16 copies (B[i]=A[i+1]) for aligned tap loads,
// 4 CTAs/SM.

#define H1 64
#define W1 64
#define CIN 256
#define CMID 128
#define H2 128
#define W2 128
#define BATCH 4

#define XP_H 66
#define XP_W 68
#define XP_CH (XP_H * XP_W)          // 4488
#define YP_H 130
#define YP_W 132
#define YP_CH (YP_H * YP_W)          // 17160

typedef unsigned long long u64;
typedef unsigned int u32;

using namespace nvcuda;

__device__ __forceinline__ u32 smem_u32(const void* p) {
    u32 a; asm("{ .reg .u64 t; cvta.to.shared.u64 t, %1; cvt.u32.u64 %0, t; }" : "=r"(a) : "l"(p));
    return a;
}
__device__ __forceinline__ void cpasync16(u32 dst, const void* src) {
    asm volatile("cp.async.ca.shared.global [%0], [%1], 16;" :: "r"(dst), "l"(src));
}
__device__ __forceinline__ void cpasync_wait() {
    asm volatile("cp.async.commit_group;\n\tcp.async.wait_group 0;" ::: "memory");
}

// ---------------- scratch globals ----------------
__device__ __align__(8) __half g_xA[BATCH * CIN * XP_CH];
__device__ __align__(8) __half g_xB[BATCH * CIN * XP_CH];    // xB[i]=xA[i+1]
__device__ __align__(8) __half g_yA[BATCH * CMID * YP_CH];
__device__ __align__(8) __half g_yB[BATCH * CMID * YP_CH];
__device__ __align__(128) __half g_w1[4 * 8 * 128 * 128];    // [par][kc][o][krow]
__device__ __align__(128) __half g_w2[9 * 128 * 128];        // [ij][o][c]

// smem: A [128][136] halves, B [128][72] halves
#define SA2 136
#define SB 72
#define OFF_A 0
#define OFF_B 34816
#define KS32 16384                       // pac phase A: fp32 [9][64] (A region)
#define OFF_KSH 53248                    // pac: half2 [9][32]
#define CONVT_SMEM 53248
#define PAC_SMEM   54400

// ---------------------------------------------------------------------------
// Prep kernels
// ---------------------------------------------------------------------------
#define NW1 (4 * 8 * 128 * 128)          // 524288
#define NW2 (9 * 128 * 128)              // 147456

__global__ void prep_w(const float* __restrict__ w1, const float* __restrict__ w2) {
    int idx = blockIdx.x * 256 + threadIdx.x;        // NW1 + NW2
    if (idx < NW1) {
        int kr = idx & 127;
        int o  = (idx >> 7) & 127;
        int kc = (idx >> 14) & 7;
        int par = idx >> 17;
        int di = par >> 1, dj = par & 1;
        int c = kc * 32 + (kr >> 2);
        int tap = kr & 3;
        int t = tap >> 1, u = tap & 1;
        g_w1[idx] = __float2half_rn(w1[(c * CMID + o) * 16 + (3 - di - 2 * t) * 4 + (3 - dj - 2 * u)]);
    } else if (idx < NW1 + NW2) {
        int k = idx - NW1;
        int c  = k & 127;
        int o  = (k >> 7) & 127;
        int ij = k >> 14;
        int i = ij / 3, j = ij % 3;
        g_w2[k] = __float2half_rn(w2[(c * CMID + o) * 9 + (2 - i) * 3 + (2 - j)]);
    }
}

__global__ void pad_xk(const float* __restrict__ x) {
    int idx = blockIdx.x * 256 + threadIdx.x;
    if (idx >= BATCH * CIN * XP_CH) return;
    int col = idx % XP_W;
    int r   = (idx / XP_W) % XP_H;
    int bc  = idx / XP_CH;
    int h = r - 1;
    bool okh = (unsigned)h < (unsigned)H1;
    float vA = (okh && (unsigned)(col - 1) < (unsigned)W1) ? x[bc * (H1 * W1) + h * W1 + col - 1] : 0.f;
    float vB = (okh && (unsigned)col < (unsigned)W1) ? x[bc * (H1 * W1) + h * W1 + col] : 0.f;
    g_xA[idx] = __float2half_rn(vA);
    g_xB[idx] = __float2half_rn(vB);
}

// zero only the 1-px frame of both y copies (interior fully written by convt)
__global__ void pad_y_border() {
    int idx = blockIdx.x * 256 + threadIdx.x;        // 512 * 788
    if (idx >= BATCH * CMID * 788) return;
    int e  = idx % 788;
    int bo = idx / 788;
    __half* bA = g_yA + (u64)bo * YP_CH;
    __half* bB = g_yB + (u64)bo * YP_CH;
    __half z = __float2half_rn(0.f);
    if (e < 132)      { bA[e] = z;                    bB[e] = z; }
    else if (e < 264) { bA[129 * YP_W + e - 132] = z; bB[129 * YP_W + e - 132] = z; }
    else {
        int t = e - 264;
        int r = 1 + (t >> 2);                        // rows 1..129? t<512 -> r 1..128
        int c = t & 3;
        // A needs cols {0,129,130,131}; B (shifted by 1) needs {0,128,129,130,131}
        // cover cols {0,128,129,130,131} minus interior-written ones for A (128 is
        // interior for A but writing zero there would corrupt) -> split:
        if (c == 0)      { bA[r * YP_W] = z;           bB[r * YP_W + 128] = z; bB[r * YP_W] = z; }
        else             { bA[r * YP_W + 128 + c] = z; bB[r * YP_W + 128 + c] = z; }
    }
}

// NOTE on pad_y_border correctness: convt writes yA at padded cols 1..128 and
// yB at cols 0..127 (base-1). So frame cols needing zero: yA {0,129,130,131},
// yB {128,129,130,131} plus yB col 0 is written only when dj+... actually
// yB[base-1] with base col>=1 -> yB cols 0..127 written. yB col 0 written when
// base col==1 (w output col 0, dj=0) -> still write zero BEFORE convt runs;
// convt then overwrites. Order: pad_y_border launches before convt, so any
// interior overwrite wins. Hence zeroing extra cells (bB col 0, bA none extra)
// is safe.

// ---------------------------------------------------------------------------
// MMA stage: A[128][136], B[128][72], 8 k-steps.
// ---------------------------------------------------------------------------
template<typename AccT>
__device__ __forceinline__ void mma_stage(const char* smem, int mo, int np, AccT (&acc)[2][2]) {
#pragma unroll
    for (int k0 = 0; k0 < 8; k0++) {
        const __half* B = (const __half*)(smem + OFF_B);
        const __half* A = (const __half*)(smem + OFF_A);
        wmma::fragment<wmma::matrix_b, 16, 16, 16, __half, wmma::row_major> bf[2];
        wmma::fragment<wmma::matrix_a, 16, 16, 16, __half, wmma::row_major> af[2];
        wmma::load_matrix_sync(bf[0], B + (k0 * 16) * SB + np, SB);
        wmma::load_matrix_sync(bf[1], B + (k0 * 16) * SB + np + 16, SB);
        wmma::load_matrix_sync(af[0], A + mo * SA2 + k0 * 16, SA2);
        wmma::load_matrix_sync(af[1], A + (mo + 16) * SA2 + k0 * 16, SA2);
#pragma unroll
        for (int m = 0; m < 2; m++)
#pragma unroll
            for (int n = 0; n < 2; n++)
                wmma::mma_sync(acc[m][n], af[m], bf[n], acc[m][n]);
    }
}

// ---------------------------------------------------------------------------
// Kernel 1: conv_transpose (parity decomposition). Block: 128o x 64px.
// K = 1024 in 8 chunks of 128 (32c x 4taps). B staging = aligned u32 copies.
// ---------------------------------------------------------------------------
__global__ __launch_bounds__(256, 4) void convt_wmma(const float* __restrict__ b1) {
    extern __shared__ __align__(128) char smem[];
    const u32 sb = smem_u32(smem);
    const int tid = threadIdx.x;
    const int wid = tid >> 5;
    const int mo = (wid & 3) * 32;
    const int np = (wid >> 2) * 32;

    const int bz = blockIdx.z;
    const int b  = bz >> 2;
    const int par = bz & 3;
    const int di = par >> 1, dj = par & 1;
    const int i0 = blockIdx.y * 8;
    const int j0 = blockIdx.x * 8;

    const int px0 = (tid & 31) * 2;
    const int r = px0 >> 3, cw = px0 & 7;
    const int tap = wid & 3;
    const int t = tap >> 1, u = tap & 1;

    const int colc = j0 + dj + cw + u;
    const int cpar = colc & 1;
    const __half* xsrc = cpar ? g_xB : g_xA;
    const u32* xw = (const u32*)(xsrc + ((u64)(b * CIN + (wid >> 2)) * XP_CH)
                                 + (i0 + di + r + t) * XP_W + (colc - cpar));
    char* bsm = smem + OFF_B + wid * (SB * 2) + px0 * 2;

    wmma::fragment<wmma::accumulator, 16, 16, 16, float> acc[2][2];
#pragma unroll
    for (int m = 0; m < 2; m++)
#pragma unroll
        for (int n = 0; n < 2; n++) wmma::fill_fragment(acc[m][n], 0.f);

    for (int kc = 0; kc < 8; kc++) {
        __syncthreads();
        {
            const __half* wA = g_w1 + (par * 8 + kc) * 16384;
#pragma unroll
            for (int q = 0; q < 8; q++) {
                int p = tid + q * 256;
                int o = p >> 4, ch = p & 15;
                cpasync16(sb + OFF_A + (u32)(o * (SA2 * 2) + ch * 16), wA + o * 128 + ch * 8);
            }
        }
        const u32* xs = xw + kc * (16 * XP_CH);
#pragma unroll
        for (int q = 0; q < 16; q++) {
            *(u32*)(bsm + q * (8 * SB * 2)) = xs[0];
            xs += XP_CH;
        }
        cpasync_wait();
        __syncthreads();

        mma_stage(smem, mo, np, acc);
    }

    // epilogue: fbuf [128][72] fp32, parity scatter into fp16 y copies
    __syncthreads();
    float* fbuf = (float*)smem;
#pragma unroll
    for (int m = 0; m < 2; m++)
#pragma unroll
        for (int n = 0; n < 2; n++)
            wmma::store_matrix_sync(fbuf + (mo + m * 16) * SB + np + n * 16,
                                    acc[m][n], SB, wmma::mem_row_major);
    __syncthreads();
    for (int idx = tid; idx < 8192; idx += 256) {
        int o = idx >> 6;
        int n = idx & 63;
        int rr = n >> 3, cc = n & 7;
        float v = fbuf[o * SB + n] + __ldg(&b1[o]);
        __half hv = __float2half_rn(v);
        u64 base = (u64)(b * CMID + o) * YP_CH
                 + (2 * (i0 + rr) + di + 1) * YP_W + 2 * (j0 + cc) + dj + 1;
        g_yA[base] = hv;
        g_yB[base - 1] = hv;
    }
}

// ---------------------------------------------------------------------------
// Kernel 2: PAC 3x3. Block: 128o x 64px (8x8 tile). 9 ij stages, K=128 each.
// ---------------------------------------------------------------------------
__global__ __launch_bounds__(256, 4) void pac_wmma(const float* __restrict__ guide,
                                                   const float* __restrict__ b2,
                                                   float* __restrict__ out) {
    extern __shared__ __align__(128) char smem[];
    const u32 sb = smem_u32(smem);
    const int tid = threadIdx.x;
    const int wid = tid >> 5;
    const int mo = (wid & 3) * 32;
    const int np = (wid >> 2) * 32;

    const int b  = blockIdx.z;
    const int h0 = blockIdx.y * 8;
    const int w0 = blockIdx.x * 8;

    float* ks32 = (float*)(smem + KS32);
    u32*   ksh  = (u32*)(smem + OFF_KSH);
    float* gs   = (float*)smem;

    // ---- Phase A: guide kernel ----
    for (int tt = tid; tt < 576; tt += 256) ks32[tt] = 0.f;

    for (int cc = 0; cc < CMID; cc += 32) {
        __syncthreads();
        for (int idx = tid; idx < 3200; idx += 256) {
            int c = idx / 100;
            int rr = (idx % 100) / 10;
            int col = idx % 10;
            int gh = h0 - 1 + rr, gw = w0 - 1 + col;
            float v = 0.f;
            if ((unsigned)gh < (unsigned)H2 && (unsigned)gw < (unsigned)W2)
                v = guide[((b * CMID + cc + c) * H2 + gh) * W2 + gw];
            gs[c * 120 + rr * 12 + col] = v;
        }
        __syncthreads();
        for (int idx = tid; idx < 576; idx += 256) {
            int ij = idx >> 6;
            int p  = idx & 63;
            int i = ij / 3, j = ij % 3;
            int rr = p >> 3, cww = p & 7;
            float s = 0.f;
#pragma unroll
            for (int c = 0; c < 32; c++) {
                float d = gs[c * 120 + (rr + i) * 12 + (cww + j)] - gs[c * 120 + (rr + 1) * 12 + (cww + 1)];
                s += d * d;
            }
            ks32[idx] += s;
        }
    }
    __syncthreads();
    for (int tt = tid; tt < 576; tt += 256) ks32[tt] = __expf(-0.5f * ks32[tt]);
    __syncthreads();
    for (int tt = tid; tt < 288; tt += 256) {
        int ij = tt >> 5, p = tt & 31;
        __half2 hk = __floats2half2_rn(ks32[ij * 64 + 2 * p], ks32[ij * 64 + 2 * p + 1]);
        ksh[tt] = *(u32*)&hk;
    }
    __syncthreads();

    // ---- Phase B: 9 ij stages ----
    const int px0 = (tid & 31) * 2;
    const int r = px0 >> 3, cw = px0 & 7;
    const __half* yAb = g_yA + (u64)(b * CMID + wid) * YP_CH;
    const __half* yBb = g_yB + (u64)(b * CMID + wid) * YP_CH;
    char* bsm = smem + OFF_B + wid * (SB * 2) + px0 * 2;

    wmma::fragment<wmma::accumulator, 16, 16, 16, float> acc[2][2];
#pragma unroll
    for (int m = 0; m < 2; m++)
#pragma unroll
        for (int n = 0; n < 2; n++) wmma::fill_fragment(acc[m][n], 0.f);

    for (int ij = 0; ij < 9; ij++) {
        const int i = ij / 3, j = ij % 3;
        __syncthreads();
        {
            const __half* wA = g_w2 + ij * 16384;
#pragma unroll
            for (int q = 0; q < 8; q++) {
                int p = tid + q * 256;
                int o = p >> 4, ch = p & 15;
                cpasync16(sb + OFF_A + (u32)(o * (SA2 * 2) + ch * 16), wA + o * 128 + ch * 8);
            }
        }
        const u32 kk = ksh[ij * 32 + (tid & 31)];
        const __half2 hk = *(const __half2*)&kk;
        const __half* ysrc = (j & 1) ? yBb : yAb;
        const u32* yw = (const u32*)(ysrc + (h0 + r + i) * YP_W + w0 + cw + ((j >> 1) << 1));
#pragma unroll
        for (int q = 0; q < 16; q++) {
            __half2 v = __hmul2(*(const __half2*)yw, hk);
            *(u32*)(bsm + q * (8 * SB * 2)) = *(u32*)&v;
            yw += 4 * YP_CH;
        }
        cpasync_wait();
        __syncthreads();

        mma_stage(smem, mo, np, acc);
    }

    // ---- Epilogue ----
    __syncthreads();
    float* fbuf = (float*)smem;
#pragma unroll
    for (int m = 0; m < 2; m++)
#pragma unroll
        for (int n = 0; n < 2; n++)
            wmma::store_matrix_sync(fbuf + (mo + m * 16) * SB + np + n * 16,
                                    acc[m][n], SB, wmma::mem_row_major);
    __syncthreads();
    for (int idx = tid; idx < 8192; idx += 256) {
        int o = idx >> 6;
        int n = idx & 63;
        float v = fbuf[o * SB + n] + __ldg(&b2[o]);
        out[((b * CMID + o) * H2 + h0 + (n >> 3)) * W2 + w0 + (n & 7)] = v;
    }
}

extern "C" void kernel_launch(void* const* d_in, const int* in_sizes, int n_in,
                              void* d_out, int out_size) {
    const float* x     = (const float*)d_in[0];
    const float* guide = (const float*)d_in[1];
    const float* w1    = (const float*)d_in[2];
    const float* b1    = (const float*)d_in[3];
    const float* w2    = (const float*)d_in[4];
    const float* b2    = (const float*)d_in[5];
    float* out = (float*)d_out;

    cudaFuncSetAttribute(convt_wmma, cudaFuncAttributeMaxDynamicSharedMemorySize, CONVT_SMEM);
    cudaFuncSetAttribute(pac_wmma, cudaFuncAttributeMaxDynamicSharedMemorySize, PAC_SMEM);

    prep_w<<<(NW1 + NW2 + 255) / 256, 256>>>(w1, w2);
    pad_xk<<<(BATCH * CIN * XP_CH + 255) / 256, 256>>>(x);
    pad_y_border<<<(BATCH * CMID * 788 + 255) / 256, 256>>>();
    convt_wmma<<<dim3(8, 8, BATCH * 4), 256, CONVT_SMEM>>>(b1);
    pac_wmma<<<dim3(16, 16, BATCH), 256, PAC_SMEM>>>(guide, b2, out);
}